// round 2
// baseline (speedup 1.0000x reference)
#include <cuda_runtime.h>
#include <math.h>
#include <stdint.h>

#define D      1024
#define L      128
#define NB     16      // number of segments (B)
#define NC     256     // logit columns: 128 (a) + 128 (b)
#define BM     64      // rows per block tile
#define KC     32      // K-chunk
#define NMAX   131072

// ---------------- device scratch (no allocations allowed) ----------------
__device__ unsigned g_segmax_u[NB];
__device__ float    g_segsum[NB];
__device__ int      g_is64;
__device__ int      g_batch32[NMAX];

// monotone float<->uint encoding for atomicMax on floats
__device__ __forceinline__ unsigned enc_f(float f) {
    unsigned b = __float_as_uint(f);
    return (b & 0x80000000u) ? ~b : (b | 0x80000000u);
}
__device__ __forceinline__ float dec_f(unsigned u) {
    return (u & 0x80000000u) ? __uint_as_float(u & 0x7FFFFFFFu)
                             : __uint_as_float(~u);
}

// ---------------- batch dtype detection + canonicalization ---------------
// batch is sorted, values in [0, 15], N ~ 1e5 -> tail values are nonzero.
// If the buffer holds int64, every odd-indexed 32-bit word (high half) is 0.
// If it holds int32, tail words are all nonzero. Only reads the first n
// 32-bit words (safe under both interpretations).
__global__ void k_detect(const unsigned* __restrict__ words, int n) {
    __shared__ int zeros;
    if (threadIdx.x == 0) zeros = 0;
    __syncthreads();
    int start = (n > 128) ? (n - 128) : 0;
    for (int j = start + threadIdx.x; j < n; j += blockDim.x)
        if ((j & 1) && words[j] == 0u) atomicAdd(&zeros, 1);
    __syncthreads();
    if (threadIdx.x == 0) g_is64 = (zeros > 32) ? 1 : 0;
}

__global__ void k_convert(const void* __restrict__ b, int n) {
    int i = blockIdx.x * blockDim.x + threadIdx.x;
    if (i >= n) return;
    if (g_is64) g_batch32[i] = (int)((const long long*)b)[i];
    else        g_batch32[i] = ((const int*)b)[i];
}

// ---------------- init: zero out-accumulator + segment scratch -----------
__global__ void k_init(float* __restrict__ out_acc) {
    int i = blockIdx.x * blockDim.x + threadIdx.x;
    int stride = gridDim.x * blockDim.x;
    for (int j = i; j < NB * D; j += stride) out_acc[j] = 0.0f;
    if (i < NB) { g_segmax_u[i] = 0u; g_segsum[i] = 0.0f; }
}

// ---------------- fused GEMM + gated-score epilogue ----------------------
// logits[r, 0:128]   = feat[r] . Wa[l]  (+ba)
// logits[r, 128:256] = feat[r] . Wb[l]  (+bb)
// score[r] = sum_l sigmoid(la)*tanh(lb)*Wc[l] + bc
__global__ __launch_bounds__(256)
void k_gemm_score(const float* __restrict__ feat,
                  const float* __restrict__ Wa, const float* __restrict__ ba,
                  const float* __restrict__ Wb, const float* __restrict__ bb,
                  const float* __restrict__ Wc, const float* __restrict__ bc,
                  float* __restrict__ score, int n)
{
    __shared__ __align__(16) union {
        struct { float As[KC][BM + 1];  float Ws[KC][NC + 4]; } p1;
        struct { float BH[BM][L + 4];   float P[BM][8];       } p2;
    } sm;

    const int t  = threadIdx.x;
    const int tx = t & 15;        // 0..15 -> 16 cols each
    const int ty = t >> 4;        // 0..15 -> 4 rows each
    const int r0 = blockIdx.x * BM;

    float acc[4][16];
#pragma unroll
    for (int i = 0; i < 4; i++)
#pragma unroll
        for (int j = 0; j < 16; j++) acc[i][j] = 0.0f;

    const int kk_ld = t & 31;
    const int rr_ld = t >> 5;     // 0..7

    for (int kc = 0; kc < D; kc += KC) {
#pragma unroll
        for (int i = 0; i < BM; i += 8) {
            int rr  = i + rr_ld;
            int row = r0 + rr;
            float v = 0.0f;
            if (row < n) v = feat[(size_t)row * D + kc + kk_ld];
            sm.p1.As[kk_ld][rr] = v;
        }
#pragma unroll
        for (int i = 0; i < NC; i += 8) {
            int c = i + rr_ld;
            float v = (c < L) ? Wa[(size_t)c * D + kc + kk_ld]
                              : Wb[(size_t)(c - L) * D + kc + kk_ld];
            sm.p1.Ws[kk_ld][c] = v;
        }
        __syncthreads();

#pragma unroll
        for (int kk = 0; kk < KC; kk++) {
            float a0 = sm.p1.As[kk][4 * ty + 0];
            float a1 = sm.p1.As[kk][4 * ty + 1];
            float a2 = sm.p1.As[kk][4 * ty + 2];
            float a3 = sm.p1.As[kk][4 * ty + 3];
            const float4* wr = reinterpret_cast<const float4*>(&sm.p1.Ws[kk][16 * tx]);
            float4 w0 = wr[0], w1 = wr[1], w2 = wr[2], w3 = wr[3];
            float w[16] = { w0.x,w0.y,w0.z,w0.w, w1.x,w1.y,w1.z,w1.w,
                            w2.x,w2.y,w2.z,w2.w, w3.x,w3.y,w3.z,w3.w };
#pragma unroll
            for (int j = 0; j < 16; j++) {
                acc[0][j] = fmaf(a0, w[j], acc[0][j]);
                acc[1][j] = fmaf(a1, w[j], acc[1][j]);
                acc[2][j] = fmaf(a2, w[j], acc[2][j]);
                acc[3][j] = fmaf(a3, w[j], acc[3][j]);
            }
        }
        __syncthreads();
    }

    // ---- epilogue ----
    if (tx >= 8) {
        int lbase = 16 * (tx - 8);
        float bbv[16];
#pragma unroll
        for (int j = 0; j < 16; j++) bbv[j] = bb[lbase + j];
#pragma unroll
        for (int i = 0; i < 4; i++)
#pragma unroll
            for (int j = 0; j < 16; j++)
                sm.p2.BH[4 * ty + i][lbase + j] = tanhf(acc[i][j] + bbv[j]);
    } else {
        int lbase = 16 * tx;
        float bav[16], wcv[16];
#pragma unroll
        for (int j = 0; j < 16; j++) { bav[j] = ba[lbase + j]; wcv[j] = Wc[lbase + j]; }
#pragma unroll
        for (int i = 0; i < 4; i++)
#pragma unroll
            for (int j = 0; j < 16; j++) {
                float s = 1.0f / (1.0f + __expf(-(acc[i][j] + bav[j])));
                acc[i][j] = s * wcv[j];
            }
    }
    __syncthreads();

    if (tx < 8) {
        int lbase = 16 * tx;
        float part[4] = {0.0f, 0.0f, 0.0f, 0.0f};
#pragma unroll
        for (int j = 0; j < 16; j++) {
#pragma unroll
            for (int i = 0; i < 4; i++)
                part[i] = fmaf(acc[i][j], sm.p2.BH[4 * ty + i][lbase + j], part[i]);
        }
#pragma unroll
        for (int i = 0; i < 4; i++) sm.p2.P[4 * ty + i][tx] = part[i];
    }
    __syncthreads();

    if (t < BM) {
        int row = r0 + t;
        if (row < n) {
            float s = bc[0];
#pragma unroll
            for (int q = 0; q < 8; q++) s += sm.p2.P[t][q];
            score[row] = s;
        }
    }
}

// ---------------- segment max -------------------------------------------
__global__ void k_segmax(const float* __restrict__ score, int n)
{
    __shared__ unsigned smx[NB];
    if (threadIdx.x < NB) smx[threadIdx.x] = 0u;
    __syncthreads();
    for (int i = blockIdx.x * blockDim.x + threadIdx.x; i < n;
         i += gridDim.x * blockDim.x) {
        atomicMax(&smx[g_batch32[i]], enc_f(score[i]));
    }
    __syncthreads();
    if (threadIdx.x < NB) atomicMax(&g_segmax_u[threadIdx.x], smx[threadIdx.x]);
}

// ---------------- segment sum of exp ------------------------------------
__global__ void k_segsum(const float* __restrict__ score, int n)
{
    __shared__ float ssm[NB];
    __shared__ float smx[NB];
    if (threadIdx.x < NB) {
        ssm[threadIdx.x] = 0.0f;
        smx[threadIdx.x] = dec_f(g_segmax_u[threadIdx.x]);
    }
    __syncthreads();
    for (int i = blockIdx.x * blockDim.x + threadIdx.x; i < n;
         i += gridDim.x * blockDim.x) {
        int b = g_batch32[i];
        atomicAdd(&ssm[b], __expf(score[i] - smx[b]));
    }
    __syncthreads();
    if (threadIdx.x < NB) atomicAdd(&g_segsum[threadIdx.x], ssm[threadIdx.x]);
}

// ---------------- final: softmax write + weighted segment reduce ---------
// batch is globally sorted, so a 64-row chunk spans few segments: keep
// register accumulators, flush on segment change via atomicAdd.
__global__ __launch_bounds__(256)
void k_final(const float* __restrict__ feat,
             const float* __restrict__ score,
             float* __restrict__ softmax_out,
             float* __restrict__ out_acc, int n)
{
    __shared__ float w_s[BM];
    __shared__ int   seg_s[BM];
    const int t  = threadIdx.x;
    const int r0 = blockIdx.x * BM;

    if (t < BM) {
        int row = r0 + t;
        if (row < n) {
            int b = g_batch32[row];
            float mx = dec_f(g_segmax_u[b]);
            float e  = __expf(score[row] - mx);
            float w  = e / (g_segsum[b] + 1e-16f);
            w_s[t] = w; seg_s[t] = b;
            softmax_out[row] = w;
        } else {
            w_s[t] = 0.0f; seg_s[t] = -1;
        }
    }
    __syncthreads();

    const int c = t * 4;              // 256 threads x float4 = 1024 cols
    float4 acc = make_float4(0.f, 0.f, 0.f, 0.f);
    int cur = seg_s[0];
    int rows = n - r0; if (rows > BM) rows = BM;

    for (int r = 0; r < rows; r++) {
        int sg = seg_s[r];
        if (sg != cur) {
            float* dst = out_acc + (size_t)cur * D + c;
            atomicAdd(dst + 0, acc.x); atomicAdd(dst + 1, acc.y);
            atomicAdd(dst + 2, acc.z); atomicAdd(dst + 3, acc.w);
            acc = make_float4(0.f, 0.f, 0.f, 0.f);
            cur = sg;
        }
        float4 f = *reinterpret_cast<const float4*>(feat + (size_t)(r0 + r) * D + c);
        float w = w_s[r];
        acc.x = fmaf(w, f.x, acc.x); acc.y = fmaf(w, f.y, acc.y);
        acc.z = fmaf(w, f.z, acc.z); acc.w = fmaf(w, f.w, acc.w);
    }
    if (cur >= 0) {
        float* dst = out_acc + (size_t)cur * D + c;
        atomicAdd(dst + 0, acc.x); atomicAdd(dst + 1, acc.y);
        atomicAdd(dst + 2, acc.z); atomicAdd(dst + 3, acc.w);
    }
}

// ---------------- launch -------------------------------------------------
extern "C" void kernel_launch(void* const* d_in, const int* in_sizes, int n_in,
                              void* d_out, int out_size)
{
    const float* feat  = (const float*)d_in[0];
    const void*  batch = d_in[1];
    const float* Wa    = (const float*)d_in[2];
    const float* ba    = (const float*)d_in[3];
    const float* Wb    = (const float*)d_in[4];
    const float* bb    = (const float*)d_in[5];
    const float* Wc    = (const float*)d_in[6];
    const float* bc    = (const float*)d_in[7];
    const int n = in_sizes[1];           // batch has N elements

    float* out      = (float*)d_out;           // [16, 1024]
    float* score    = out + NB * D;            // [N]
    float* softmax  = score + n;               // [N]
    float* featcopy = softmax + n;             // [N, 1024]

    const int gb = (n + BM - 1) / BM;

    k_detect<<<1, 128>>>((const unsigned*)batch, n);
    k_convert<<<(n + 255) / 256, 256>>>(batch, n);
    k_init<<<64, 256>>>(out);
    k_gemm_score<<<gb, 256>>>(feat, Wa, ba, Wb, bb, Wc, bc, score, n);
    cudaMemcpyAsync(featcopy, feat, (size_t)n * D * sizeof(float),
                    cudaMemcpyDeviceToDevice);
    k_segmax<<<256, 256>>>(score, n);
    k_segsum<<<256, 256>>>(score, n);
    k_final<<<gb, 256>>>(feat, score, softmax, out, n);
}

// round 3
// speedup vs baseline: 6.5190x; 6.5190x over previous
#include <cuda_runtime.h>
#include <math.h>
#include <stdint.h>

#define D      1024
#define L      128
#define NB     16      // number of segments (B)
#define NC     256     // logit columns: 128 (a) + 128 (b)
#define BM     64      // rows per GEMM block tile
#define KC     16      // K-chunk (floats)
#define NK     (D / KC)
#define STAGES 3
#define NMAX   131072
#define EPI_S  132     // epilogue smem stride (= 4 mod 32 -> conflict-free strided reads)

// ---------------- device scratch (no allocations allowed) ----------------
__device__ unsigned g_segmax_u[NB];
__device__ float    g_segsum[NB];
__device__ int      g_is64;
__device__ int      g_batch32[NMAX];

// monotone float<->uint encoding for atomicMax on floats
__device__ __forceinline__ unsigned enc_f(float f) {
    unsigned b = __float_as_uint(f);
    return (b & 0x80000000u) ? ~b : (b | 0x80000000u);
}
__device__ __forceinline__ float dec_f(unsigned u) {
    return (u & 0x80000000u) ? __uint_as_float(u & 0x7FFFFFFFu)
                             : __uint_as_float(~u);
}

__device__ __forceinline__ uint32_t smem_u32(const void* p) {
    return (uint32_t)__cvta_generic_to_shared(p);
}
__device__ __forceinline__ void cp16(uint32_t dst, const void* src, int sz) {
    asm volatile("cp.async.cg.shared.global [%0], [%1], 16, %2;"
                 :: "r"(dst), "l"(src), "r"(sz));
}
__device__ __forceinline__ void mma_tf32(float* c, const uint32_t* a,
                                         uint32_t b0, uint32_t b1) {
    asm volatile("mma.sync.aligned.m16n8k8.row.col.f32.tf32.tf32.f32 "
                 "{%0,%1,%2,%3}, {%4,%5,%6,%7}, {%8,%9}, {%0,%1,%2,%3};"
                 : "+f"(c[0]), "+f"(c[1]), "+f"(c[2]), "+f"(c[3])
                 : "r"(a[0]), "r"(a[1]), "r"(a[2]), "r"(a[3]),
                   "r"(b0), "r"(b1));
}
// XOR-chunk swizzle: row r, col k (k < 16); 4-float chunks rotated by (r>>1)&3
__device__ __forceinline__ int swz(int r, int k) {
    return r * KC + ((((k >> 2) + ((r >> 1) & 3)) & 3) << 2) + (k & 3);
}

// ---------------- batch dtype detection + canonicalization ---------------
__global__ void k_detect(const unsigned* __restrict__ words, int n) {
    __shared__ int zeros;
    if (threadIdx.x == 0) zeros = 0;
    __syncthreads();
    int start = (n > 128) ? (n - 128) : 0;
    for (int j = start + threadIdx.x; j < n; j += blockDim.x)
        if ((j & 1) && words[j] == 0u) atomicAdd(&zeros, 1);
    __syncthreads();
    if (threadIdx.x == 0) g_is64 = (zeros > 32) ? 1 : 0;
}

__global__ void k_convert(const void* __restrict__ b, int n) {
    int i = blockIdx.x * blockDim.x + threadIdx.x;
    if (i >= n) return;
    if (g_is64) g_batch32[i] = (int)((const long long*)b)[i];
    else        g_batch32[i] = ((const int*)b)[i];
}

// ---------------- init -----------------------------------------------------
__global__ void k_init(float* __restrict__ out_acc) {
    int i = blockIdx.x * blockDim.x + threadIdx.x;
    int stride = gridDim.x * blockDim.x;
    for (int j = i; j < NB * D; j += stride) out_acc[j] = 0.0f;
    if (i < NB) { g_segmax_u[i] = 0u; g_segsum[i] = 0.0f; }
}

// ---------------- TF32 tensor-core GEMM + fused gated-score epilogue -------
// C[64 x 256] = feat_tile . [Wa|Wb]^T ; then
// score[r] = sum_l sigmoid(Ca[r,l]+ba[l]) * tanh(Cb[r,l]+bb[l]) * Wc[l] + bc
__global__ __launch_bounds__(256, 2)
void k_gemm_mma(const float* __restrict__ feat,
                const float* __restrict__ Wa, const float* __restrict__ ba,
                const float* __restrict__ Wb, const float* __restrict__ bb,
                const float* __restrict__ Wc, const float* __restrict__ bc,
                float* __restrict__ score, int n)
{
    extern __shared__ float sm[];
    float* As_base = sm;                         // [STAGES][BM*KC]
    float* Bs_base = sm + STAGES * BM * KC;      // [STAGES][NC*KC]
    float* a_act   = sm;                         // epilogue reuse [BM][EPI_S]
    float* b_act   = sm + BM * EPI_S;

    const int t      = threadIdx.x;
    const int lane   = t & 31;
    const int wid    = t >> 5;
    const int g      = lane >> 2;
    const int tg     = lane & 3;
    const int warp_m = (wid & 1) * 32;
    const int warp_n = (wid >> 1) * 64;
    const int r0     = blockIdx.x * BM;

    float cacc[2][8][4];
#pragma unroll
    for (int i = 0; i < 2; i++)
#pragma unroll
        for (int j = 0; j < 8; j++)
#pragma unroll
            for (int q = 0; q < 4; q++) cacc[i][j][q] = 0.0f;

    // -------- loader precompute --------
    const int ar  = t >> 2, aq = t & 3;
    const int aqq = (aq + ((ar >> 1) & 3)) & 3;
    const float* a_src = feat + (size_t)(r0 + ar) * D + 4 * aq;
    const int a_sz = (r0 + ar < n) ? 16 : 0;
    const uint32_t a_dst = smem_u32(As_base + ar * KC + aqq * 4);

    uint32_t b_dst[4];
    const float* b_src[4];
#pragma unroll
    for (int i = 0; i < 4; i++) {
        int id = t + 256 * i;
        int nr = id >> 2, q = id & 3;
        int qq = (q + ((nr >> 1) & 3)) & 3;
        b_dst[i] = smem_u32(Bs_base + nr * KC + qq * 4);
        b_src[i] = ((nr < L) ? (Wa + (size_t)nr * D)
                             : (Wb + (size_t)(nr - L) * D)) + 4 * q;
    }

    auto load_stage = [&](int slot, int kc) {
        uint32_t soA = (uint32_t)(slot * BM * KC * 4);
        uint32_t soB = (uint32_t)(slot * NC * KC * 4);
        cp16(a_dst + soA, a_src + kc, a_sz);
#pragma unroll
        for (int i = 0; i < 4; i++)
            cp16(b_dst[i] + soB, b_src[i] + kc, 16);
    };

    auto compute_stage = [&](int slot) {
        const float* As = As_base + slot * (BM * KC);
        const float* Bs = Bs_base + slot * (NC * KC);
#pragma unroll
        for (int ks = 0; ks < 2; ks++) {
            const int k0 = 8 * ks;
            uint32_t af[2][4];
#pragma unroll
            for (int mi = 0; mi < 2; mi++) {
                int r1 = warp_m + 16 * mi + g;
                af[mi][0] = __float_as_uint(As[swz(r1,     k0 + tg)]);
                af[mi][1] = __float_as_uint(As[swz(r1 + 8, k0 + tg)]);
                af[mi][2] = __float_as_uint(As[swz(r1,     k0 + 4 + tg)]);
                af[mi][3] = __float_as_uint(As[swz(r1 + 8, k0 + 4 + tg)]);
            }
#pragma unroll
            for (int nj = 0; nj < 8; nj++) {
                int nr = warp_n + 8 * nj + g;
                uint32_t b0 = __float_as_uint(Bs[swz(nr, k0 + tg)]);
                uint32_t b1 = __float_as_uint(Bs[swz(nr, k0 + 4 + tg)]);
                mma_tf32(cacc[0][nj], af[0], b0, b1);
                mma_tf32(cacc[1][nj], af[1], b0, b1);
            }
        }
    };

    // -------- 3-stage cp.async pipeline --------
#pragma unroll
    for (int s = 0; s < STAGES - 1; s++) {
        load_stage(s, s * KC);
        asm volatile("cp.async.commit_group;" ::: "memory");
    }
    for (int ki = 0; ki < NK; ki++) {
        asm volatile("cp.async.wait_group 1;" ::: "memory");
        __syncthreads();
        int kn = ki + STAGES - 1;
        if (kn < NK) load_stage(kn % STAGES, kn * KC);
        asm volatile("cp.async.commit_group;" ::: "memory");
        compute_stage(ki % STAGES);
    }
    asm volatile("cp.async.wait_group 0;" ::: "memory");
    __syncthreads();   // free pipeline smem for epilogue union

    // -------- epilogue: activations to smem --------
    const bool is_a = (warp_n < L);
#pragma unroll
    for (int nj = 0; nj < 8; nj++) {
        int c0 = warp_n + 8 * nj + 2 * tg;
        float p0, p1, q0 = 0.f, q1 = 0.f;
        if (is_a) { p0 = ba[c0]; p1 = ba[c0 + 1]; q0 = Wc[c0]; q1 = Wc[c0 + 1]; }
        else      { p0 = bb[c0 - L]; p1 = bb[c0 - L + 1]; }
#pragma unroll
        for (int mi = 0; mi < 2; mi++) {
            int r1 = warp_m + 16 * mi + g;
            int r2 = r1 + 8;
            const float* v = cacc[mi][nj];
            if (is_a) {
                a_act[r1 * EPI_S + c0]     = q0 / (1.0f + __expf(-(v[0] + p0)));
                a_act[r1 * EPI_S + c0 + 1] = q1 / (1.0f + __expf(-(v[1] + p1)));
                a_act[r2 * EPI_S + c0]     = q0 / (1.0f + __expf(-(v[2] + p0)));
                a_act[r2 * EPI_S + c0 + 1] = q1 / (1.0f + __expf(-(v[3] + p1)));
            } else {
                int l = c0 - L;
                b_act[r1 * EPI_S + l]     = tanhf(v[0] + p0);
                b_act[r1 * EPI_S + l + 1] = tanhf(v[1] + p1);
                b_act[r2 * EPI_S + l]     = tanhf(v[2] + p0);
                b_act[r2 * EPI_S + l + 1] = tanhf(v[3] + p1);
            }
        }
    }
    __syncthreads();

    // -------- score reduction: 4 lanes per row, stride-4 over l --------
    {
        int rr = t >> 2, pp = t & 3;
        float s = 0.0f;
#pragma unroll
        for (int i = 0; i < 32; i++) {
            int l = pp + 4 * i;
            s += a_act[rr * EPI_S + l] * b_act[rr * EPI_S + l];
        }
        s += __shfl_xor_sync(0xFFFFFFFFu, s, 1);
        s += __shfl_xor_sync(0xFFFFFFFFu, s, 2);
        if (pp == 0 && r0 + rr < n) score[r0 + rr] = s + bc[0];
    }
}

// ---------------- segment max ----------------------------------------------
__global__ void k_segmax(const float* __restrict__ score, int n)
{
    __shared__ unsigned smx[NB];
    if (threadIdx.x < NB) smx[threadIdx.x] = 0u;
    __syncthreads();
    for (int i = blockIdx.x * blockDim.x + threadIdx.x; i < n;
         i += gridDim.x * blockDim.x) {
        atomicMax(&smx[g_batch32[i]], enc_f(score[i]));
    }
    __syncthreads();
    if (threadIdx.x < NB) atomicMax(&g_segmax_u[threadIdx.x], smx[threadIdx.x]);
}

// ---------------- segment sum of exp ---------------------------------------
__global__ void k_segsum(const float* __restrict__ score, int n)
{
    __shared__ float ssm[NB];
    __shared__ float smx[NB];
    if (threadIdx.x < NB) {
        ssm[threadIdx.x] = 0.0f;
        smx[threadIdx.x] = dec_f(g_segmax_u[threadIdx.x]);
    }
    __syncthreads();
    for (int i = blockIdx.x * blockDim.x + threadIdx.x; i < n;
         i += gridDim.x * blockDim.x) {
        int b = g_batch32[i];
        atomicAdd(&ssm[b], __expf(score[i] - smx[b]));
    }
    __syncthreads();
    if (threadIdx.x < NB) atomicAdd(&g_segsum[threadIdx.x], ssm[threadIdx.x]);
}

// ---------------- final: softmax + weighted segment reduce + feature copy ---
__global__ __launch_bounds__(256)
void k_final(const float* __restrict__ feat,
             const float* __restrict__ score,
             float* __restrict__ softmax_out,
             float* __restrict__ featcopy,
             float* __restrict__ out_acc, int n)
{
    __shared__ float w_s[BM];
    __shared__ int   seg_s[BM];
    const int t  = threadIdx.x;
    const int r0 = blockIdx.x * BM;

    if (t < BM) {
        int row = r0 + t;
        if (row < n) {
            int b = g_batch32[row];
            float mx = dec_f(g_segmax_u[b]);
            float e  = __expf(score[row] - mx);
            float w  = e / (g_segsum[b] + 1e-16f);
            w_s[t] = w; seg_s[t] = b;
            softmax_out[row] = w;
        } else {
            w_s[t] = 0.0f; seg_s[t] = -1;
        }
    }
    __syncthreads();

    const int c = t * 4;              // 256 threads x float4 = 1024 cols
    float4 acc = make_float4(0.f, 0.f, 0.f, 0.f);
    int cur = seg_s[0];
    int rows = n - r0; if (rows > BM) rows = BM;

    for (int r = 0; r < rows; r++) {
        int sg = seg_s[r];
        if (sg != cur) {
            float* dst = out_acc + (size_t)cur * D + c;
            atomicAdd(dst + 0, acc.x); atomicAdd(dst + 1, acc.y);
            atomicAdd(dst + 2, acc.z); atomicAdd(dst + 3, acc.w);
            acc = make_float4(0.f, 0.f, 0.f, 0.f);
            cur = sg;
        }
        size_t off = (size_t)(r0 + r) * D + c;
        float4 f = *reinterpret_cast<const float4*>(feat + off);
        *reinterpret_cast<float4*>(featcopy + off) = f;   // fused copy-out
        float w = w_s[r];
        acc.x = fmaf(w, f.x, acc.x); acc.y = fmaf(w, f.y, acc.y);
        acc.z = fmaf(w, f.z, acc.z); acc.w = fmaf(w, f.w, acc.w);
    }
    if (cur >= 0) {
        float* dst = out_acc + (size_t)cur * D + c;
        atomicAdd(dst + 0, acc.x); atomicAdd(dst + 1, acc.y);
        atomicAdd(dst + 2, acc.z); atomicAdd(dst + 3, acc.w);
    }
}

// ---------------- launch ----------------------------------------------------
extern "C" void kernel_launch(void* const* d_in, const int* in_sizes, int n_in,
                              void* d_out, int out_size)
{
    const float* feat  = (const float*)d_in[0];
    const void*  batch = d_in[1];
    const float* Wa    = (const float*)d_in[2];
    const float* ba    = (const float*)d_in[3];
    const float* Wb    = (const float*)d_in[4];
    const float* bb    = (const float*)d_in[5];
    const float* Wc    = (const float*)d_in[6];
    const float* bc    = (const float*)d_in[7];
    const int n = in_sizes[1];           // batch has N elements

    float* out      = (float*)d_out;           // [16, 1024]
    float* score    = out + NB * D;            // [N]
    float* softmax  = score + n;               // [N]
    float* featcopy = softmax + n;             // [N, 1024]

    const int gb = (n + BM - 1) / BM;
    const int dsmem = 2 * BM * EPI_S * (int)sizeof(float);   // 67584 > pipeline 61440

    cudaFuncSetAttribute(k_gemm_mma,
                         cudaFuncAttributeMaxDynamicSharedMemorySize, dsmem);

    k_detect<<<1, 128>>>((const unsigned*)batch, n);
    k_convert<<<(n + 255) / 256, 256>>>(batch, n);
    k_init<<<64, 256>>>(out);
    k_gemm_mma<<<gb, 256, dsmem>>>(feat, Wa, ba, Wb, bb, Wc, bc, score, n);
    k_segmax<<<256, 256>>>(score, n);
    k_segsum<<<256, 256>>>(score, n);
    k_final<<<gb, 256>>>(feat, score, softmax, featcopy, out, n);
}

// round 4
// speedup vs baseline: 7.3615x; 1.1292x over previous
#include <cuda_runtime.h>
#include <math.h>
#include <stdint.h>

#define D      1024
#define L      128
#define NB     16      // number of segments (B)
#define NC     256     // logit columns: 128 (a) + 128 (b)
#define BM     128     // rows per GEMM block tile
#define KC     32      // K-chunk (floats)
#define NK     (D / KC)        // 32
#define STAGES 3
#define NMAX   131072
#define FBM    64      // rows per block in k_final
#define EPI_S  132     // epilogue smem stride

// ---------------- device scratch (no allocations allowed) ----------------
__device__ unsigned g_segmax_u[NB];
__device__ float    g_segsum[NB];
__device__ int      g_is64;
__device__ int      g_batch32[NMAX];

__device__ __forceinline__ unsigned enc_f(float f) {
    unsigned b = __float_as_uint(f);
    return (b & 0x80000000u) ? ~b : (b | 0x80000000u);
}
__device__ __forceinline__ float dec_f(unsigned u) {
    return (u & 0x80000000u) ? __uint_as_float(u & 0x7FFFFFFFu)
                             : __uint_as_float(~u);
}
__device__ __forceinline__ uint32_t smem_u32(const void* p) {
    return (uint32_t)__cvta_generic_to_shared(p);
}
__device__ __forceinline__ void cp16(uint32_t dst, const void* src, int sz) {
    asm volatile("cp.async.cg.shared.global [%0], [%1], 16, %2;"
                 :: "r"(dst), "l"(src), "r"(sz));
}
__device__ __forceinline__ void mma_tf32(float* c, const uint32_t* a,
                                         uint32_t b0, uint32_t b1) {
    asm volatile("mma.sync.aligned.m16n8k8.row.col.f32.tf32.tf32.f32 "
                 "{%0,%1,%2,%3}, {%4,%5,%6,%7}, {%8,%9}, {%0,%1,%2,%3};"
                 : "+f"(c[0]), "+f"(c[1]), "+f"(c[2]), "+f"(c[3])
                 : "r"(a[0]), "r"(a[1]), "r"(a[2]), "r"(a[3]),
                   "r"(b0), "r"(b1));
}
// XOR-chunk swizzle for 32-float rows: phys = r*32 + ((k/4 ^ (r&7))*4) + k%4
__device__ __forceinline__ int swz(int r, int k) {
    return r * KC + ((((k >> 2) ^ (r & 7)) & 7) << 2) + (k & 3);
}

// ---------------- batch dtype detection + canonicalization ---------------
__global__ void k_detect(const unsigned* __restrict__ words, int n) {
    __shared__ int zeros;
    if (threadIdx.x == 0) zeros = 0;
    __syncthreads();
    int start = (n > 128) ? (n - 128) : 0;
    for (int j = start + threadIdx.x; j < n; j += blockDim.x)
        if ((j & 1) && words[j] == 0u) atomicAdd(&zeros, 1);
    __syncthreads();
    if (threadIdx.x == 0) g_is64 = (zeros > 32) ? 1 : 0;
}
__global__ void k_convert(const void* __restrict__ b, int n) {
    int i = blockIdx.x * blockDim.x + threadIdx.x;
    if (i >= n) return;
    if (g_is64) g_batch32[i] = (int)((const long long*)b)[i];
    else        g_batch32[i] = ((const int*)b)[i];
}
__global__ void k_init(float* __restrict__ out_acc) {
    int i = blockIdx.x * blockDim.x + threadIdx.x;
    int stride = gridDim.x * blockDim.x;
    for (int j = i; j < NB * D; j += stride) out_acc[j] = 0.0f;
    if (i < NB) { g_segmax_u[i] = 0u; g_segsum[i] = 0.0f; }
}

// ---------------- TF32 tensor-core GEMM + fused gated-score epilogue -------
// block tile: 128 rows x 256 cols, 512 threads, warp grid 4(m) x 4(n),
// warp tile 32x64. 3-stage cp.async pipeline, KC=32.
__global__ __launch_bounds__(512, 1)
void k_gemm_mma(const float* __restrict__ feat,
                const float* __restrict__ Wa, const float* __restrict__ ba,
                const float* __restrict__ Wb, const float* __restrict__ bb,
                const float* __restrict__ Wc, const float* __restrict__ bc,
                float* __restrict__ score, int n)
{
    extern __shared__ float sm[];
    float* As_base = sm;                           // [STAGES][BM*KC]
    float* Bs_base = sm + STAGES * BM * KC;        // [STAGES][NC*KC]
    float* a_act   = sm;                           // epilogue reuse [BM][EPI_S]
    float* score_s = sm + BM * EPI_S;              // [BM][2]

    const int t      = threadIdx.x;
    const int lane   = t & 31;
    const int wid    = t >> 5;
    const int g      = lane >> 2;
    const int tg     = lane & 3;
    const int warp_m = (wid & 3) * 32;
    const int warp_n = (wid >> 2) * 64;
    const int r0     = blockIdx.x * BM;

    float cacc[2][8][4];
#pragma unroll
    for (int i = 0; i < 2; i++)
#pragma unroll
        for (int j = 0; j < 8; j++)
#pragma unroll
            for (int q = 0; q < 4; q++) cacc[i][j][q] = 0.0f;

    // -------- loader precompute (coalesced: 8 threads cover one 32-f row) ----
    uint32_t a_dst[2]; const float* a_src[2]; int a_sz[2];
#pragma unroll
    for (int i = 0; i < 2; i++) {
        int id = t + 512 * i;
        int ar = id >> 3, ac = id & 7;
        int row = r0 + ar;
        int safe = (row < n) ? row : (n - 1);
        a_src[i] = feat + (size_t)safe * D + 4 * ac;
        a_sz[i]  = (row < n) ? 16 : 0;
        a_dst[i] = smem_u32(As_base + ar * KC + (((ac ^ (ar & 7)) & 7) << 2));
    }
    uint32_t b_dst[4]; const float* b_src[4];
#pragma unroll
    for (int i = 0; i < 4; i++) {
        int id = t + 512 * i;
        int nr = id >> 3, c = id & 7;
        b_src[i] = ((nr < L) ? (Wa + (size_t)nr * D)
                             : (Wb + (size_t)(nr - L) * D)) + 4 * c;
        b_dst[i] = smem_u32(Bs_base + nr * KC + (((c ^ (nr & 7)) & 7) << 2));
    }

    auto load_stage = [&](int slot, int kc) {
        uint32_t soA = (uint32_t)(slot * BM * KC * 4);
        uint32_t soB = (uint32_t)(slot * NC * KC * 4);
#pragma unroll
        for (int i = 0; i < 2; i++) cp16(a_dst[i] + soA, a_src[i] + kc, a_sz[i]);
#pragma unroll
        for (int i = 0; i < 4; i++) cp16(b_dst[i] + soB, b_src[i] + kc, 16);
    };

    auto compute_stage = [&](int slot) {
        const float* As = As_base + slot * (BM * KC);
        const float* Bs = Bs_base + slot * (NC * KC);
#pragma unroll
        for (int ks = 0; ks < 4; ks++) {
            const int k0 = 8 * ks;
            uint32_t af[2][4];
#pragma unroll
            for (int mi = 0; mi < 2; mi++) {
                int r1 = warp_m + 16 * mi + g;
                af[mi][0] = __float_as_uint(As[swz(r1,     k0 + tg)]);
                af[mi][1] = __float_as_uint(As[swz(r1 + 8, k0 + tg)]);
                af[mi][2] = __float_as_uint(As[swz(r1,     k0 + 4 + tg)]);
                af[mi][3] = __float_as_uint(As[swz(r1 + 8, k0 + 4 + tg)]);
            }
#pragma unroll
            for (int nj = 0; nj < 8; nj++) {
                int nr = warp_n + 8 * nj + g;
                uint32_t b0 = __float_as_uint(Bs[swz(nr, k0 + tg)]);
                uint32_t b1 = __float_as_uint(Bs[swz(nr, k0 + 4 + tg)]);
                mma_tf32(cacc[0][nj], af[0], b0, b1);
                mma_tf32(cacc[1][nj], af[1], b0, b1);
            }
        }
    };

    // -------- 3-stage pipeline --------
#pragma unroll
    for (int s = 0; s < STAGES - 1; s++) {
        load_stage(s, s * KC);
        asm volatile("cp.async.commit_group;" ::: "memory");
    }
    for (int ki = 0; ki < NK; ki++) {
        asm volatile("cp.async.wait_group 1;" ::: "memory");
        __syncthreads();                       // data ki visible; ki-1 compute done
        int kn = ki + STAGES - 1;
        if (kn < NK) load_stage(kn % STAGES, kn * KC);
        asm volatile("cp.async.commit_group;" ::: "memory");
        compute_stage(ki % STAGES);
    }
    asm volatile("cp.async.wait_group 0;" ::: "memory");
    __syncthreads();   // all compute done; smem now reusable for epilogue

    // -------- epilogue phase 1: a-warps stage Wc*sigmoid into smem ----------
    const bool is_a = (warp_n < L);
    if (is_a) {
#pragma unroll
        for (int nj = 0; nj < 8; nj++) {
            int c0 = warp_n + 8 * nj + 2 * tg;
            float p0 = ba[c0], p1 = ba[c0 + 1];
            float q0 = Wc[c0], q1 = Wc[c0 + 1];
#pragma unroll
            for (int mi = 0; mi < 2; mi++) {
                int r1 = warp_m + 16 * mi + g;
                int r2 = r1 + 8;
                const float* v = cacc[mi][nj];
                a_act[r1 * EPI_S + c0]     = q0 / (1.0f + __expf(-(v[0] + p0)));
                a_act[r1 * EPI_S + c0 + 1] = q1 / (1.0f + __expf(-(v[1] + p1)));
                a_act[r2 * EPI_S + c0]     = q0 / (1.0f + __expf(-(v[2] + p0)));
                a_act[r2 * EPI_S + c0 + 1] = q1 / (1.0f + __expf(-(v[3] + p1)));
            }
        }
    }
    __syncthreads();

    // -------- phase 2: b-warps fuse tanh, multiply, reduce ------------------
    if (!is_a) {
        int slot = (warp_n - L) >> 6;   // 0 or 1
        float s[2][2] = {{0.f, 0.f}, {0.f, 0.f}};
#pragma unroll
        for (int nj = 0; nj < 8; nj++) {
            int l0 = (warp_n - L) + 8 * nj + 2 * tg;
            float p0 = bb[l0], p1 = bb[l0 + 1];
#pragma unroll
            for (int mi = 0; mi < 2; mi++) {
                int r1 = warp_m + 16 * mi + g;
                int r2 = r1 + 8;
                const float* v = cacc[mi][nj];
                s[mi][0] += tanhf(v[0] + p0) * a_act[r1 * EPI_S + l0]
                          + tanhf(v[1] + p1) * a_act[r1 * EPI_S + l0 + 1];
                s[mi][1] += tanhf(v[2] + p0) * a_act[r2 * EPI_S + l0]
                          + tanhf(v[3] + p1) * a_act[r2 * EPI_S + l0 + 1];
            }
        }
#pragma unroll
        for (int mi = 0; mi < 2; mi++)
#pragma unroll
            for (int q = 0; q < 2; q++) {
                s[mi][q] += __shfl_xor_sync(0xFFFFFFFFu, s[mi][q], 1);
                s[mi][q] += __shfl_xor_sync(0xFFFFFFFFu, s[mi][q], 2);
            }
        if (tg == 0) {
#pragma unroll
            for (int mi = 0; mi < 2; mi++) {
                int r1 = warp_m + 16 * mi + g;
                score_s[r1 * 2 + slot]       = s[mi][0];
                score_s[(r1 + 8) * 2 + slot] = s[mi][1];
            }
        }
    }
    __syncthreads();

    if (t < BM) {
        int row = r0 + t;
        if (row < n)
            score[row] = score_s[t * 2] + score_s[t * 2 + 1] + bc[0];
    }
}

// ---------------- segment max ----------------------------------------------
__global__ void k_segmax(const float* __restrict__ score, int n)
{
    __shared__ unsigned smx[NB];
    if (threadIdx.x < NB) smx[threadIdx.x] = 0u;
    __syncthreads();
    for (int i = blockIdx.x * blockDim.x + threadIdx.x; i < n;
         i += gridDim.x * blockDim.x) {
        atomicMax(&smx[g_batch32[i]], enc_f(score[i]));
    }
    __syncthreads();
    if (threadIdx.x < NB) atomicMax(&g_segmax_u[threadIdx.x], smx[threadIdx.x]);
}

// ---------------- segment sum of exp ---------------------------------------
__global__ void k_segsum(const float* __restrict__ score, int n)
{
    __shared__ float ssm[NB];
    __shared__ float smx[NB];
    if (threadIdx.x < NB) {
        ssm[threadIdx.x] = 0.0f;
        smx[threadIdx.x] = dec_f(g_segmax_u[threadIdx.x]);
    }
    __syncthreads();
    for (int i = blockIdx.x * blockDim.x + threadIdx.x; i < n;
         i += gridDim.x * blockDim.x) {
        int b = g_batch32[i];
        atomicAdd(&ssm[b], __expf(score[i] - smx[b]));
    }
    __syncthreads();
    if (threadIdx.x < NB) atomicAdd(&g_segsum[threadIdx.x], ssm[threadIdx.x]);
}

// ---------------- final: softmax + weighted segment reduce + feature copy ---
__global__ __launch_bounds__(256)
void k_final(const float* __restrict__ feat,
             const float* __restrict__ score,
             float* __restrict__ softmax_out,
             float* __restrict__ featcopy,
             float* __restrict__ out_acc, int n)
{
    __shared__ float w_s[FBM];
    __shared__ int   seg_s[FBM];
    const int t  = threadIdx.x;
    const int r0 = blockIdx.x * FBM;

    if (t < FBM) {
        int row = r0 + t;
        if (row < n) {
            int b = g_batch32[row];
            float mx = dec_f(g_segmax_u[b]);
            float e  = __expf(score[row] - mx);
            float w  = e / (g_segsum[b] + 1e-16f);
            w_s[t] = w; seg_s[t] = b;
            softmax_out[row] = w;
        } else {
            w_s[t] = 0.0f; seg_s[t] = -1;
        }
    }
    __syncthreads();

    const int c = t * 4;
    float4 acc = make_float4(0.f, 0.f, 0.f, 0.f);
    int cur = seg_s[0];
    int rows = n - r0; if (rows > FBM) rows = FBM;

    for (int r = 0; r < rows; r++) {
        int sg = seg_s[r];
        if (sg != cur) {
            float* dst = out_acc + (size_t)cur * D + c;
            atomicAdd(dst + 0, acc.x); atomicAdd(dst + 1, acc.y);
            atomicAdd(dst + 2, acc.z); atomicAdd(dst + 3, acc.w);
            acc = make_float4(0.f, 0.f, 0.f, 0.f);
            cur = sg;
        }
        size_t off = (size_t)(r0 + r) * D + c;
        float4 f = *reinterpret_cast<const float4*>(feat + off);
        *reinterpret_cast<float4*>(featcopy + off) = f;
        float w = w_s[r];
        acc.x = fmaf(w, f.x, acc.x); acc.y = fmaf(w, f.y, acc.y);
        acc.z = fmaf(w, f.z, acc.z); acc.w = fmaf(w, f.w, acc.w);
    }
    if (cur >= 0) {
        float* dst = out_acc + (size_t)cur * D + c;
        atomicAdd(dst + 0, acc.x); atomicAdd(dst + 1, acc.y);
        atomicAdd(dst + 2, acc.z); atomicAdd(dst + 3, acc.w);
    }
}

// ---------------- launch ----------------------------------------------------
extern "C" void kernel_launch(void* const* d_in, const int* in_sizes, int n_in,
                              void* d_out, int out_size)
{
    const float* feat  = (const float*)d_in[0];
    const void*  batch = d_in[1];
    const float* Wa    = (const float*)d_in[2];
    const float* ba    = (const float*)d_in[3];
    const float* Wb    = (const float*)d_in[4];
    const float* bb    = (const float*)d_in[5];
    const float* Wc    = (const float*)d_in[6];
    const float* bc    = (const float*)d_in[7];
    const int n = in_sizes[1];

    float* out      = (float*)d_out;           // [16, 1024]
    float* score    = out + NB * D;            // [N]
    float* softmax  = score + n;               // [N]
    float* featcopy = softmax + n;             // [N, 1024]

    const int gb  = (n + BM - 1) / BM;
    const int gbf = (n + FBM - 1) / FBM;
    const int dsmem = STAGES * (BM + NC) * KC * (int)sizeof(float); // 147456

    static int configured = -1;
    if (configured < 0) {
        cudaFuncSetAttribute(k_gemm_mma,
                             cudaFuncAttributeMaxDynamicSharedMemorySize, dsmem);
        configured = 1;
    }

    k_detect<<<1, 128>>>((const unsigned*)batch, n);
    k_convert<<<(n + 255) / 256, 256>>>(batch, n);
    k_init<<<64, 256>>>(out);
    k_gemm_mma<<<gb, 512, dsmem>>>(feat, Wa, ba, Wb, bb, Wc, bc, score, n);
    k_segmax<<<256, 256>>>(score, n);
    k_segsum<<<256, 256>>>(score, n);
    k_final<<<gbf, 256>>>(feat, score, softmax, featcopy, out, n);
}